// round 17
// baseline (speedup 1.0000x reference)
#include <cuda_runtime.h>
#include <cstdint>
#include <math.h>

#define KNBR  32
#define D     128
#define T     512
#define B_TOT 32768
#define NQUAD (B_TOT / 4)   // 4 rows (2 pairs) per macro-iteration

// smem layout (float offsets)
#define OFF_HN    0        // 2 * 16384 double-buffered (4 rows x 4096)
#define OFF_HE    32768    // 2 * 512
#define OFF_MSK   33792    // 2 * 128 ints
#define OFF_VS    34048    // 256 (v_ego | v_nbr)
#define OFF_EGO2  34304    // 512: ego2[pair*256 + 2*d + r]
#define OFF_AGG2  34816    // 512
#define OFF_REDD  35328    // 2048: 16 warps x 128
#define OFF_REDE  37376    // 2 * 4096: DOUBLE-BUFFERED proj results (2048 u64 each)
#define OFF_LOG   45568    // 128
#define OFF_ATT   45696    // 128
#define SMEM_FLOATS 45824
#define SMEM_BYTES (SMEM_FLOATS * 4)

__device__ float g_v[2 * D];   // [0:128) v_ego = W_msg^T a_ego, [128:256) v_nbr

// ---------------- prologue: v = W_msg^T @ a ----------------
__global__ void prep_kernel(const float* __restrict__ Wmsg,
                            const float* __restrict__ Wattn) {
    int d = threadIdx.x;   // 128 threads
    float ve = 0.f, vn = 0.f;
    #pragma unroll 8
    for (int e = 0; e < D; e++) {
        float w = Wmsg[e * D + d];
        ve = fmaf(Wattn[e], w, ve);
        vn = fmaf(Wattn[D + e], w, vn);
    }
    g_v[d] = ve;
    g_v[D + d] = vn;
}

// ---------------- cp.async helpers ----------------
__device__ __forceinline__ void cp16(uint32_t dst, const void* src) {
    asm volatile("cp.async.cg.shared.global [%0], [%1], 16;" :: "r"(dst), "l"(src));
}
__device__ __forceinline__ void cp_commit() { asm volatile("cp.async.commit_group;"); }
__device__ __forceinline__ void cp_wait1()  { asm volatile("cp.async.wait_group 1;" ::: "memory"); }
__device__ __forceinline__ void cp_waitall(){ asm volatile("cp.async.wait_all;" ::: "memory"); }

__device__ __forceinline__ void prefetch_quad(int q, int buf, int tid, uint32_t smem_u32,
                                              const float* __restrict__ h_nei,
                                              const float* __restrict__ h_ego,
                                              const int*   __restrict__ nbr_mask) {
    const float* src = h_nei + (size_t)q * 16384;
    uint32_t hdst = smem_u32 + (uint32_t)(OFF_HN + buf * 16384) * 4u;
    #pragma unroll
    for (int i = 0; i < 8; i++) {                        // 4096 float4
        int idx = tid + i * T;
        cp16(hdst + (uint32_t)idx * 16u, src + idx * 4);
    }
    if (tid < 128)
        cp16(smem_u32 + (uint32_t)(OFF_HE + buf * 512 + tid * 4) * 4u,
             h_ego + (size_t)q * 512 + tid * 4);
    if (tid < 32)
        cp16(smem_u32 + (uint32_t)(OFF_MSK + buf * 128 + tid * 4) * 4u,
             nbr_mask + (size_t)q * 128 + tid * 4);
}

// ---------------- packed f32x2 dot of a 4-float fragment with a 4-float vector ----------------
__device__ __forceinline__ float dot2(ulonglong2 f, ulonglong2 v) {
    unsigned long long acc = 0ull;
    asm("fma.rn.f32x2 %0, %1, %2, %3;" : "=l"(acc) : "l"(f.x), "l"(v.x), "l"(acc));
    asm("fma.rn.f32x2 %0, %1, %2, %3;" : "=l"(acc) : "l"(f.y), "l"(v.y), "l"(acc));
    unsigned int lo, hi;
    asm("mov.b64 {%0,%1}, %2;" : "=r"(lo), "=r"(hi) : "l"(acc));
    return __uint_as_float(lo) + __uint_as_float(hi);
}

// ---------------- FFMA2 projection (R14-verified): 2 outputs (e6, e6+64) x 32 inputs, both pairs ----------------
// xq: u64[256], batch-packed {row0,row1}: xq[pair*128 + d]
// wreg[0..31]  = W[e6][c0..c0+32) ; wreg[32..63] = W[e6+64][c0..c0+32)
// writes 4 u64 results: rE[slot_e0], rE[slot_e1], rE[1024+slot_e0], rE[1024+slot_e1]
__device__ __forceinline__ void proj2x32(const unsigned long long* __restrict__ xq,
                                         const float* __restrict__ wreg,
                                         int c0,
                                         unsigned long long* __restrict__ rE,
                                         int slot_e0, int slot_e1) {
    unsigned long long a00 = 0ull, a01 = 0ull, a10 = 0ull, a11 = 0ull;
    #pragma unroll
    for (int dd = 0; dd < 32; dd += 2) {
        ulonglong2 x0 = *(const ulonglong2*)&xq[c0 + dd];         // pair0: d, d+1
        ulonglong2 x1 = *(const ulonglong2*)&xq[128 + c0 + dd];   // pair1: d, d+1
        unsigned long long w0, w1, w0b, w1b;
        unsigned int wa  = __float_as_uint(wreg[dd]);
        unsigned int wb  = __float_as_uint(wreg[32 + dd]);
        unsigned int wa1 = __float_as_uint(wreg[dd + 1]);
        unsigned int wb1 = __float_as_uint(wreg[32 + dd + 1]);
        asm("mov.b64 %0, {%1,%1};" : "=l"(w0)  : "r"(wa));
        asm("mov.b64 %0, {%1,%1};" : "=l"(w1)  : "r"(wb));
        asm("mov.b64 %0, {%1,%1};" : "=l"(w0b) : "r"(wa1));
        asm("mov.b64 %0, {%1,%1};" : "=l"(w1b) : "r"(wb1));
        asm("fma.rn.f32x2 %0, %1, %2, %3;" : "=l"(a00) : "l"(w0),  "l"(x0.x), "l"(a00));
        asm("fma.rn.f32x2 %0, %1, %2, %3;" : "=l"(a01) : "l"(w1),  "l"(x0.x), "l"(a01));
        asm("fma.rn.f32x2 %0, %1, %2, %3;" : "=l"(a10) : "l"(w0),  "l"(x1.x), "l"(a10));
        asm("fma.rn.f32x2 %0, %1, %2, %3;" : "=l"(a11) : "l"(w1),  "l"(x1.x), "l"(a11));
        asm("fma.rn.f32x2 %0, %1, %2, %3;" : "=l"(a00) : "l"(w0b), "l"(x0.y), "l"(a00));
        asm("fma.rn.f32x2 %0, %1, %2, %3;" : "=l"(a01) : "l"(w1b), "l"(x0.y), "l"(a01));
        asm("fma.rn.f32x2 %0, %1, %2, %3;" : "=l"(a10) : "l"(w0b), "l"(x1.y), "l"(a10));
        asm("fma.rn.f32x2 %0, %1, %2, %3;" : "=l"(a11) : "l"(w1b), "l"(x1.y), "l"(a11));
    }
    rE[slot_e0]        = a00;
    rE[slot_e1]        = a01;
    rE[1024 + slot_e0] = a10;
    rE[1024 + slot_e1] = a11;
}

// ---------------- deferred combine + tanh + store (threads 256..511) ----------------
__device__ __forceinline__ void combine_store(int tid, int qc, const float* __restrict__ redEbuf,
                                              float bb, float* __restrict__ out) {
    int ct = tid - 256, pr = ct >> 7, dd = ct & 127;
    const float2* r = (const float2*)redEbuf + pr * 1024;
    float2 r0 = r[0 * 128 + dd];
    float2 r1 = r[1 * 128 + dd];
    float2 r2 = r[2 * 128 + dd];
    float2 r3 = r[3 * 128 + dd];
    float2 r4 = r[4 * 128 + dd];
    float2 r5 = r[5 * 128 + dd];
    float2 r6 = r[6 * 128 + dd];
    float2 r7 = r[7 * 128 + dd];
    float sx = ((r0.x + r1.x) + (r2.x + r3.x)) + ((r4.x + r5.x) + (r6.x + r7.x));
    float sy = ((r0.y + r1.y) + (r2.y + r3.y)) + ((r4.y + r5.y) + (r6.y + r7.y));
    float o0 = tanhf(sx + bb);
    float o1 = tanhf(sy + bb);
    size_t row = ((size_t)4 * qc + 2 * pr) * D;
    out[row + dd]     = o0;
    out[row + D + dd] = o1;
}

// ---------------- main fused kernel ----------------
__global__ void __launch_bounds__(T, 1)
gat_kernel(const float* __restrict__ h_ego, const float* __restrict__ h_nei,
           const int*   __restrict__ nbr_mask,
           const float* __restrict__ Wmsg, const float* __restrict__ Wself,
           const float* __restrict__ bself, float* __restrict__ out) {
    extern __shared__ float sm[];
    float* hn    = sm + OFF_HN;
    float* he    = sm + OFF_HE;
    int*   msk   = (int*)(sm + OFF_MSK);
    float* vs    = sm + OFF_VS;
    float* ego2  = sm + OFF_EGO2;
    float* agg2  = sm + OFF_AGG2;
    float* redD  = sm + OFF_REDD;
    float* redE  = sm + OFF_REDE;
    float* logit = sm + OFF_LOG;
    float* attn  = sm + OFF_ATT;

    const int tid  = threadIdx.x;
    const int lane = tid & 31;
    const int warp = tid >> 5;
    const int rr   = warp >> 2;           // row within quad (0..3)
    const int kq   = (warp & 3) * 8;      // 8 k's per warp

    // projection tile: m = matrix (0: Wmsg / agg2, 1: Wself / ego2)
    const int m    = tid >> 8;            // 0..1
    const int h    = (tid >> 6) & 3;      // input quarter
    const int e6   = tid & 63;            // output pair base (outputs e6 and e6+64)
    const int c0   = h * 32;              // first input dim
    const int slot_e0 = h * 256 + m * 128 + e6;
    const int slot_e1 = slot_e0 + 64;

    // W slices in registers: rows e6 and e6+64, cols [c0, c0+32)
    const float* Wsrc = (m == 0) ? Wmsg : Wself;
    float wreg[64];
    #pragma unroll
    for (int j = 0; j < 32; j += 4) {
        float4 t4 = *(const float4*)&Wsrc[e6 * D + c0 + j];
        wreg[j] = t4.x; wreg[j + 1] = t4.y; wreg[j + 2] = t4.z; wreg[j + 3] = t4.w;
        float4 t5 = *(const float4*)&Wsrc[(e6 + 64) * D + c0 + j];
        wreg[32 + j] = t5.x; wreg[33 + j] = t5.y; wreg[34 + j] = t5.z; wreg[35 + j] = t5.w;
    }
    if (tid < 2 * D) vs[tid] = g_v[tid];
    float bb = __ldg(bself + (tid & 127));
    __syncthreads();

    const uint32_t smem_u32 = (uint32_t)__cvta_generic_to_shared(sm);
    const float NEG_INF = __int_as_float(0xff800000);
    const int G = gridDim.x;

    int q = blockIdx.x;
    int s = 0;
    int it = 0;
    int lastq = -1;
    if (q < NQUAD) prefetch_quad(q, 0, tid, smem_u32, h_nei, h_ego, nbr_mask);
    cp_commit();

    for (; q < NQUAD; q += G, s ^= 1, it++) {
        int qn = q + G;
        if (qn < NQUAD) prefetch_quad(qn, s ^ 1, tid, smem_u32, h_nei, h_ego, nbr_mask);
        cp_commit();
        cp_wait1();
        __syncthreads();   // B0: buffer s ready; prev iteration's proj results visible

        const float* hnb  = &hn[s * 16384];
        const float* heb  = &he[s * 512];
        const int*   mskb = &msk[s * 128];
        const float* hb   = &hnb[rr * 4096 + kq * 128];

        // ---- stage fragments ONCE (as u64 pairs); neighbor dots + pe, all packed ----
        ulonglong2 f0 = *(const ulonglong2*)&hb[0 * 128 + lane * 4];
        ulonglong2 f1 = *(const ulonglong2*)&hb[1 * 128 + lane * 4];
        ulonglong2 f2 = *(const ulonglong2*)&hb[2 * 128 + lane * 4];
        ulonglong2 f3 = *(const ulonglong2*)&hb[3 * 128 + lane * 4];
        ulonglong2 f4 = *(const ulonglong2*)&hb[4 * 128 + lane * 4];
        ulonglong2 f5 = *(const ulonglong2*)&hb[5 * 128 + lane * 4];
        ulonglong2 f6 = *(const ulonglong2*)&hb[6 * 128 + lane * 4];
        ulonglong2 f7 = *(const ulonglong2*)&hb[7 * 128 + lane * 4];
        {
            ulonglong2 vN2 = *(const ulonglong2*)&vs[D + lane * 4];
            ulonglong2 vE2 = *(const ulonglong2*)&vs[lane * 4];
            ulonglong2 eg2 = *(const ulonglong2*)&heb[rr * 128 + lane * 4];
            float a0 = dot2(f0, vN2);
            float a1 = dot2(f1, vN2);
            float a2 = dot2(f2, vN2);
            float a3 = dot2(f3, vN2);
            float a4 = dot2(f4, vN2);
            float a5 = dot2(f5, vN2);
            float a6 = dot2(f6, vN2);
            float a7 = dot2(f7, vN2);
            float pe = dot2(eg2, vE2);   // this row's ego logit contribution

            const unsigned FULL = 0xffffffffu;
            // pe: standard xor-reduce (independent chain, interleaves with butterfly)
            #pragma unroll
            for (int o = 16; o > 0; o >>= 1) pe += __shfl_xor_sync(FULL, pe, o);

            // pair-combining butterfly: 8 values -> 1 per lane-class
            bool h16 = (lane & 16) != 0;
            float s0, o0;
            s0 = h16 ? a1 : a0; o0 = h16 ? a0 : a1;
            float b0 = s0 + __shfl_xor_sync(FULL, o0, 16);
            s0 = h16 ? a3 : a2; o0 = h16 ? a2 : a3;
            float b1 = s0 + __shfl_xor_sync(FULL, o0, 16);
            s0 = h16 ? a5 : a4; o0 = h16 ? a4 : a5;
            float b2 = s0 + __shfl_xor_sync(FULL, o0, 16);
            s0 = h16 ? a7 : a6; o0 = h16 ? a6 : a7;
            float b3 = s0 + __shfl_xor_sync(FULL, o0, 16);

            bool h8 = (lane & 8) != 0;
            s0 = h8 ? b1 : b0; o0 = h8 ? b0 : b1;
            float c0v = s0 + __shfl_xor_sync(FULL, o0, 8);
            s0 = h8 ? b3 : b2; o0 = h8 ? b2 : b3;
            float c1v = s0 + __shfl_xor_sync(FULL, o0, 8);

            bool h4 = (lane & 4) != 0;
            s0 = h4 ? c1v : c0v; o0 = h4 ? c0v : c1v;
            float dsum = s0 + __shfl_xor_sync(FULL, o0, 4);

            dsum += __shfl_xor_sync(FULL, dsum, 2);
            dsum += __shfl_xor_sync(FULL, dsum, 1);

            if ((lane & 3) == 0) {
                int kl = ((lane >> 4) & 1) | (((lane >> 3) & 1) << 1) | (((lane >> 2) & 1) << 2);
                float lg = dsum + pe;
                lg = (lg > 0.f) ? lg : 0.2f * lg;                     // leaky_relu
                int mv = mskb[rr * KNBR + kq + kl];
                logit[rr * KNBR + kq + kl] = (mv > 0) ? lg : NEG_INF; // mask fused here
            }
        }
        // pack ego batch-major (threads 256..511 handle 2 each) — needed before A1
        if (tid >= 256) {
            int t = tid - 256;
            #pragma unroll
            for (int i = 0; i < 2; i++) {
                int idx = t + i * 256;          // 0..511
                int r = idx >> 7, dd = idx & 127;
                ego2[(r >> 1) * 256 + 2 * dd + (r & 1)] = heb[r * 128 + dd];
            }
        }
        __syncthreads();   // A1: logits (pe+leaky+mask applied) + ego2 ready

        // ---- softmax (warps 0..3, shortened chain) || ego projection (warps 8..15) ----
        if (warp < 4) {
            float x = logit[warp * KNBR + lane];
            float mx = x;
            #pragma unroll
            for (int o = 16; o > 0; o >>= 1) mx = fmaxf(mx, __shfl_xor_sync(0xffffffffu, mx, o));
            float ee = (x == NEG_INF) ? 0.f : __expf(x - mx);
            float ss = ee;
            #pragma unroll
            for (int o = 16; o > 0; o >>= 1) ss += __shfl_xor_sync(0xffffffffu, ss, o);
            attn[warp * KNBR + lane] = (ss > 0.f) ? (ee / ss) : 0.f;
        } else if (tid >= 256) {
            // ego @ Wself^T for both pairs — independent of attention
            proj2x32((const unsigned long long*)ego2, wreg, c0,
                     (unsigned long long*)(redE + s * 4096), slot_e0, slot_e1);
        }
        __syncthreads();   // A2: attn ready

        // ---- weighted partial aggregation, FFMA2-packed, from HELD u64 fragments ----
        {
            float4 atv0 = *(const float4*)&attn[rr * KNBR + kq];
            float4 atv1 = *(const float4*)&attn[rr * KNBR + kq + 4];
            unsigned long long acc01 = 0ull, acc23 = 0ull;
            #define AGG2(AK, F) { unsigned long long akk; \
                asm("mov.b64 %0, {%1,%1};" : "=l"(akk) : "r"(__float_as_uint(AK))); \
                asm("fma.rn.f32x2 %0, %1, %2, %3;" : "=l"(acc01) : "l"(akk), "l"((F).x), "l"(acc01)); \
                asm("fma.rn.f32x2 %0, %1, %2, %3;" : "=l"(acc23) : "l"(akk), "l"((F).y), "l"(acc23)); }
            AGG2(atv0.x, f0)
            AGG2(atv0.y, f1)
            AGG2(atv0.z, f2)
            AGG2(atv0.w, f3)
            AGG2(atv1.x, f4)
            AGG2(atv1.y, f5)
            AGG2(atv1.z, f6)
            AGG2(atv1.w, f7)
            #undef AGG2
            ulonglong2 st; st.x = acc01; st.y = acc23;
            ((ulonglong2*)redD)[warp * 32 + lane] = st;   // same float4 layout as before
        }
        __syncthreads();   // A3

        // ---- reduce 4 partials per (row,dim) -> batch-packed agg2 ----
        {
            int r  = tid >> 7;        // 0..3 (row)
            int dd = tid & 127;
            const float* rb = &redD[(4 * r) * 128 + dd];
            agg2[(r >> 1) * 256 + 2 * dd + (r & 1)] =
                rb[0] + rb[128] + rb[256] + rb[384];
        }
        __syncthreads();   // A4

        // ---- msg proj (threads 0..255, fma) || deferred combine of PREV quad
        //      (threads 256..511: LDS/MUFU/STG — pipe-mixed window) ----
        if (tid < 256) {
            proj2x32((const unsigned long long*)agg2, wreg, c0,
                     (unsigned long long*)(redE + s * 4096), slot_e0, slot_e1);
        } else if (it > 0) {
            combine_store(tid, q - G, redE + (s ^ 1) * 4096, bb, out);
        }
        lastq = q;
        // no A5: redE[s] consumed next iteration after B0 (or in epilogue)
    }
    cp_waitall();
    __syncthreads();   // final proj results visible
    if (lastq >= 0 && tid >= 256)
        combine_store(tid, lastq, redE + (s ^ 1) * 4096, bb, out);
}

// ---------------- launch ----------------
extern "C" void kernel_launch(void* const* d_in, const int* in_sizes, int n_in,
                              void* d_out, int out_size) {
    const float* h_ego  = (const float*)d_in[0];
    const float* h_nei  = (const float*)d_in[1];
    const int*   nmask  = (const int*)  d_in[2];
    const float* Wmsg   = (const float*)d_in[3];
    const float* Wattn  = (const float*)d_in[4];
    const float* Wself  = (const float*)d_in[5];
    const float* bself  = (const float*)d_in[6];
    float* out = (float*)d_out;

    int sms = 0;
    cudaDeviceGetAttribute(&sms, cudaDevAttrMultiProcessorCount, 0);
    if (sms <= 0) sms = 148;

    cudaFuncSetAttribute(gat_kernel, cudaFuncAttributeMaxDynamicSharedMemorySize, SMEM_BYTES);

    prep_kernel<<<1, D>>>(Wmsg, Wattn);
    gat_kernel<<<sms, T, SMEM_BYTES>>>(h_ego, h_nei, nmask, Wmsg, Wself, bself, out);
}